// round 13
// baseline (speedup 1.0000x reference)
#include <cuda_runtime.h>
#include <cuda_fp16.h>
#include <mma.h>
#include <cstdint>

using namespace nvcuda;

// Problem dims
#define B_ 4
#define S_ 2048
#define E_ 2048
#define H_ 16
#define DH_ 128
#define F_ 8192
#define MTOK (B_*S_)   // 8192 token rows

// ---------------- scratch (static device globals; no allocations) -------------
__device__ float  g_sc  [(size_t)B_*H_*S_*S_];        // 1GB scores f32
__device__ float  g_x2  [(size_t)MTOK*E_];            // 64MB

__device__ __half h_probs[(size_t)B_*H_*S_*S_];       // 512MB f16 probs
__device__ __half h_y   [(size_t)MTOK*E_];            // 32MB (y / y2)
__device__ __half h_q   [(size_t)MTOK*E_];
__device__ __half h_k   [(size_t)MTOK*E_];
__device__ __half h_v   [(size_t)MTOK*E_];
__device__ __half h_attn[(size_t)MTOK*E_];
__device__ __half h_act [(size_t)MTOK*F_];            // 128MB
__device__ __half h_wq  [(size_t)E_*E_];              // [N][K] f16
__device__ __half h_wk  [(size_t)E_*E_];
__device__ __half h_wv  [(size_t)E_*E_];
__device__ __half h_wo  [(size_t)E_*E_];
__device__ __half h_wg  [(size_t)E_*F_];              // [8192][2048]
__device__ __half h_wl  [(size_t)E_*F_];
__device__ __half h_wout[(size_t)F_*E_];              // [2048][8192]

// single TU-wide dynamic smem symbol
extern __shared__ char dynsmem[];

// ---------------- cp.async helpers --------------------------------------------
__device__ __forceinline__ void cpa16(void* dst, const void* src) {
    unsigned d = (unsigned)__cvta_generic_to_shared(dst);
    asm volatile("cp.async.cg.shared.global [%0], [%1], 16;\n" :: "r"(d), "l"(src));
}
__device__ __forceinline__ void cpa_commit() {
    asm volatile("cp.async.commit_group;\n" ::: "memory");
}
template<int N>
__device__ __forceinline__ void cpa_wait() {
    asm volatile("cp.async.wait_group %0;\n" :: "n"(N) : "memory");
}

// ---------------- fp16 WMMA GEMM, cp.async 3-stage, single-barrier loop --------
// C = A(f16) * B(f16) (+R f32). TRANS_B: B is [N][K] row-major.
// OUT_HALF: write f16 via smem-staged convert epilogue; else f32.
// BM=BN=128, BK=64. 256 threads = 8 warps (2x4), warp tile 64x32 (m16n16k16).
#define BM 128
#define BN 128
#define BK 64
#define HLDA 72                    // A/Bt smem row pitch (halves)
#define HLDB 136                   // non-trans B smem row pitch
#define A_H (BM*HLDA)              // 9216 halves
#define B_H (BM*HLDA)              // 9216 halves (covers both layouts)
#define STG_H (A_H + B_H)          // 18432 halves = 36864 B
#define NSTAGE 3
#define SMEM_BYTES (NSTAGE*STG_H*2)   // 110592 B
#define CLDS 136                   // f32 epilogue staging pitch

template<bool TRANS_B, bool CAUSAL_SKIP, bool CAUSAL_KLIM, bool HAS_RES, bool OUT_HALF>
__global__ void __launch_bounds__(256, 2)
gemm_f16(const __half* __restrict__ A, const __half* __restrict__ Bm,
         void* __restrict__ Cv, const float* __restrict__ R,
         int K, int lda, int ldb, int ldc,
         long long sAo, long long sAi,
         long long sBo, long long sBi,
         long long sCo, long long sCi)
{
    if (CAUSAL_SKIP && blockIdx.x > blockIdx.y) return;

    __half* smem = (__half*)dynsmem;

    const int zb = blockIdx.z >> 4, zi = blockIdx.z & 15;
    const long long offA = zb*sAo + (long long)zi*sAi;
    const long long offB = zb*sBo + (long long)zi*sBi;
    const long long offC = zb*sCo + (long long)zi*sCi;

    const __half* Ag = A + offA + (long long)blockIdx.y * BM * lda;
    const int n0 = blockIdx.x * BN;
    const __half* Bg = TRANS_B ? (Bm + offB + (long long)n0 * ldb)
                               : (Bm + offB + n0);

    int kEnd = K;
    if (CAUSAL_KLIM) kEnd = min(K, (int)(blockIdx.y + 1) * BM);
    const int nk = kEnd / BK;

    const int tid = threadIdx.x;
    const int warpId  = tid >> 5;
    const int warpRow = warpId >> 2;   // 0..1
    const int warpCol = warpId & 3;    // 0..3

    wmma::fragment<wmma::accumulator, 16, 16, 16, float> acc[4][2];
#pragma unroll
    for (int i = 0; i < 4; i++)
#pragma unroll
        for (int j = 0; j < 2; j++)
            wmma::fill_fragment(acc[i][j], 0.f);

    auto issue = [&](int kc, int st) {
        __half* da = smem + st * STG_H;
        __half* db = da + A_H;
#pragma unroll
        for (int t = 0; t < 4; t++) {            // A: 1024 x 16B
            int qq = tid + t * 256;
            int row = qq >> 3, c16 = qq & 7;
            cpa16(da + row * HLDA + c16 * 8,
                  Ag + (long long)row * lda + kc * BK + c16 * 8);
        }
        if (TRANS_B) {
#pragma unroll
            for (int t = 0; t < 4; t++) {        // Bt: [128 n-rows][64 k]
                int qq = tid + t * 256;
                int row = qq >> 3, c16 = qq & 7;
                cpa16(db + row * HLDA + c16 * 8,
                      Bg + (long long)row * ldb + kc * BK + c16 * 8);
            }
        } else {
#pragma unroll
            for (int t = 0; t < 4; t++) {        // B: [64 k-rows][128 n]
                int qq = tid + t * 256;
                int row = qq >> 4, c16 = qq & 15;
                cpa16(db + row * HLDB + c16 * 8,
                      Bg + (long long)(kc * BK + row) * ldb + c16 * 8);
            }
        }
    };

    auto compute = [&](int buf) {
        const __half* Asb = smem + buf * STG_H + warpRow * 64 * HLDA;
        const __half* Bsb = smem + buf * STG_H + A_H;
#pragma unroll
        for (int ks = 0; ks < BK/16; ks++) {
            wmma::fragment<wmma::matrix_a, 16, 16, 16, __half, wmma::row_major> af[4];
#pragma unroll
            for (int i = 0; i < 4; i++)
                wmma::load_matrix_sync(af[i], Asb + i*16*HLDA + ks*16, HLDA);
            if (TRANS_B) {
                wmma::fragment<wmma::matrix_b, 16, 16, 16, __half, wmma::col_major> bf[2];
#pragma unroll
                for (int j = 0; j < 2; j++)
                    wmma::load_matrix_sync(bf[j], Bsb + (warpCol*32 + j*16)*HLDA + ks*16, HLDA);
#pragma unroll
                for (int i = 0; i < 4; i++)
#pragma unroll
                    for (int j = 0; j < 2; j++)
                        wmma::mma_sync(acc[i][j], af[i], bf[j], acc[i][j]);
            } else {
                wmma::fragment<wmma::matrix_b, 16, 16, 16, __half, wmma::row_major> bf[2];
#pragma unroll
                for (int j = 0; j < 2; j++)
                    wmma::load_matrix_sync(bf[j], Bsb + ks*16*HLDB + warpCol*32 + j*16, HLDB);
#pragma unroll
                for (int i = 0; i < 4; i++)
#pragma unroll
                    for (int j = 0; j < 2; j++)
                        wmma::mma_sync(acc[i][j], af[i], bf[j], acc[i][j]);
            }
        }
    };

    // prologue: prefetch 2 stages
    issue(0, 0); cpa_commit();
    if (1 < nk) issue(1, 1);
    cpa_commit();

    // single-barrier mainloop: issue next stage right after the barrier
    for (int kc = 0; kc < nk; kc++) {
        cpa_wait<NSTAGE-2>();        // stage kc landed (this thread's groups)
        __syncthreads();             // ...and everyone else's
        if (kc + 2 < nk) issue(kc + 2, (kc + 2) % NSTAGE);
        cpa_commit();
        compute(kc % NSTAGE);
    }

    const long long crow = (long long)blockIdx.y * BM + warpRow * 64;
    const int ccol = n0 + warpCol * 32;

    if (!OUT_HALF) {
        float* Cg = (float*)Cv + offC;
#pragma unroll
        for (int i = 0; i < 4; i++) {
#pragma unroll
            for (int j = 0; j < 2; j++) {
                long long offc = (crow + i*16) * ldc + ccol + j*16;
                if (HAS_RES) {
                    wmma::fragment<wmma::accumulator, 16, 16, 16, float> rf;
                    wmma::load_matrix_sync(rf, R + offc, ldc, wmma::mem_row_major);
#pragma unroll
                    for (int e = 0; e < rf.num_elements; e++)
                        acc[i][j].x[e] += rf.x[e];
                }
                wmma::store_matrix_sync(Cg + offc, acc[i][j], ldc, wmma::mem_row_major);
            }
        }
    } else {
        cpa_wait<0>();
        __syncthreads();
        float* cs = (float*)dynsmem;   // [128][CLDS]
#pragma unroll
        for (int i = 0; i < 4; i++)
#pragma unroll
            for (int j = 0; j < 2; j++)
                wmma::store_matrix_sync(cs + (warpRow*64 + i*16)*CLDS + warpCol*32 + j*16,
                                        acc[i][j], CLDS, wmma::mem_row_major);
        __syncthreads();
        __half* Ch = (__half*)Cv + offC;
        const long long row0 = (long long)blockIdx.y * BM;
#pragma unroll
        for (int t = 0; t < 8; t++) {
            int qq = tid + t * 256;
            int row = qq >> 4, c = (qq & 15) * 8;
            float4 lo = *(float4*)(cs + row * CLDS + c);
            float4 hi = *(float4*)(cs + row * CLDS + c + 4);
            __half2 p0 = __floats2half2_rn(lo.x, lo.y);
            __half2 p1 = __floats2half2_rn(lo.z, lo.w);
            __half2 p2 = __floats2half2_rn(hi.x, hi.y);
            __half2 p3 = __floats2half2_rn(hi.z, hi.w);
            uint4 pk;
            pk.x = *(unsigned*)&p0; pk.y = *(unsigned*)&p1;
            pk.z = *(unsigned*)&p2; pk.w = *(unsigned*)&p3;
            *(uint4*)(Ch + (row0 + row) * ldc + n0 + c) = pk;
        }
    }
}

// ---------------- fused FFN1: act = gelu(A@Wg^T) * (A@Wl^T), f16 out -----------
// Shared A tile, two B streams, dual accumulators, gelu*mul epilogue.
#define F1_STG_H (3*BM*HLDA)                 // A + Bg + Bl per stage (halves)
#define F1_SMEM (NSTAGE*F1_STG_H*2)          // 165888 B

__global__ void __launch_bounds__(256, 1)
gemm_ffn1(const __half* __restrict__ A, const __half* __restrict__ Wg,
          const __half* __restrict__ Wl, __half* __restrict__ Out,
          int K, int ldout)
{
    __half* smem = (__half*)dynsmem;

    const __half* Ag  = A  + (size_t)blockIdx.y * BM * K;
    const int n0 = blockIdx.x * BN;
    const __half* Bgg = Wg + (size_t)n0 * K;
    const __half* Blg = Wl + (size_t)n0 * K;
    const int nk = K / BK;

    const int tid = threadIdx.x;
    const int warpId  = tid >> 5;
    const int warpRow = warpId >> 2;
    const int warpCol = warpId & 3;

    wmma::fragment<wmma::accumulator, 16, 16, 16, float> accG[4][2], accL[4][2];
#pragma unroll
    for (int i = 0; i < 4; i++)
#pragma unroll
        for (int j = 0; j < 2; j++) {
            wmma::fill_fragment(accG[i][j], 0.f);
            wmma::fill_fragment(accL[i][j], 0.f);
        }

    auto issue = [&](int kc, int st) {
        __half* da = smem + st * F1_STG_H;
        __half* dg = da + A_H;
        __half* dl = dg + A_H;
#pragma unroll
        for (int t = 0; t < 4; t++) {
            int qq = tid + t * 256;
            int row = qq >> 3, c16 = qq & 7;
            cpa16(da + row * HLDA + c16 * 8, Ag  + (long long)row * K + kc * BK + c16 * 8);
            cpa16(dg + row * HLDA + c16 * 8, Bgg + (long long)row * K + kc * BK + c16 * 8);
            cpa16(dl + row * HLDA + c16 * 8, Blg + (long long)row * K + kc * BK + c16 * 8);
        }
    };

    auto compute = [&](int buf) {
        const __half* Asb = smem + buf * F1_STG_H + warpRow * 64 * HLDA;
        const __half* Gsb = smem + buf * F1_STG_H + A_H;
        const __half* Lsb = Gsb + A_H;
#pragma unroll
        for (int ks = 0; ks < BK/16; ks++) {
            wmma::fragment<wmma::matrix_a, 16, 16, 16, __half, wmma::row_major> af[4];
#pragma unroll
            for (int i = 0; i < 4; i++)
                wmma::load_matrix_sync(af[i], Asb + i*16*HLDA + ks*16, HLDA);
            {
                wmma::fragment<wmma::matrix_b, 16, 16, 16, __half, wmma::col_major> bf[2];
#pragma unroll
                for (int j = 0; j < 2; j++)
                    wmma::load_matrix_sync(bf[j], Gsb + (warpCol*32 + j*16)*HLDA + ks*16, HLDA);
#pragma unroll
                for (int i = 0; i < 4; i++)
#pragma unroll
                    for (int j = 0; j < 2; j++)
                        wmma::mma_sync(accG[i][j], af[i], bf[j], accG[i][j]);
            }
            {
                wmma::fragment<wmma::matrix_b, 16, 16, 16, __half, wmma::col_major> bf[2];
#pragma unroll
                for (int j = 0; j < 2; j++)
                    wmma::load_matrix_sync(bf[j], Lsb + (warpCol*32 + j*16)*HLDA + ks*16, HLDA);
#pragma unroll
                for (int i = 0; i < 4; i++)
#pragma unroll
                    for (int j = 0; j < 2; j++)
                        wmma::mma_sync(accL[i][j], af[i], bf[j], accL[i][j]);
            }
        }
    };

    issue(0, 0); cpa_commit();
    issue(1, 1); cpa_commit();
    for (int kc = 0; kc < nk; kc++) {
        cpa_wait<NSTAGE-2>();
        __syncthreads();
        if (kc + 2 < nk) issue(kc + 2, (kc + 2) % NSTAGE);
        cpa_commit();
        compute(kc % NSTAGE);
    }

    // epilogue: stage both accumulator sets, gelu*mul, store f16
    cpa_wait<0>();
    __syncthreads();
    float* csG = (float*)dynsmem;            // [128][CLDS]
    float* csL = csG + 128*CLDS;             // [128][CLDS]
#pragma unroll
    for (int i = 0; i < 4; i++)
#pragma unroll
        for (int j = 0; j < 2; j++) {
            wmma::store_matrix_sync(csG + (warpRow*64 + i*16)*CLDS + warpCol*32 + j*16,
                                    accG[i][j], CLDS, wmma::mem_row_major);
            wmma::store_matrix_sync(csL + (warpRow*64 + i*16)*CLDS + warpCol*32 + j*16,
                                    accL[i][j], CLDS, wmma::mem_row_major);
        }
    __syncthreads();
    const long long row0 = (long long)blockIdx.y * BM;
#pragma unroll
    for (int t = 0; t < 8; t++) {
        int qq = tid + t * 256;
        int row = qq >> 4, c = (qq & 15) * 8;
        float g[8], l[8];
        *(float4*)(g)   = *(float4*)(csG + row * CLDS + c);
        *(float4*)(g+4) = *(float4*)(csG + row * CLDS + c + 4);
        *(float4*)(l)   = *(float4*)(csL + row * CLDS + c);
        *(float4*)(l+4) = *(float4*)(csL + row * CLDS + c + 4);
        __half hv[8];
#pragma unroll
        for (int e = 0; e < 8; e++) {
            float a = g[e];
            a = 0.5f * a * (1.f + erff(a * 0.70710678118654752f)) * l[e];
            hv[e] = __float2half(a);
        }
        *(uint4*)(Out + (row0 + row) * ldout + n0 + c) = *(uint4*)hv;
    }
}

// ---------------- transpose + f32->f16 convert ---------------------------------
__global__ void tcvt_kernel(const float* __restrict__ in, __half* __restrict__ out,
                            int Rr, int Cc)
{
    __shared__ float t[32][33];
    const int x = blockIdx.x * 32 + threadIdx.x;
#pragma unroll
    for (int i = 0; i < 4; i++) {
        int yy = blockIdx.y * 32 + threadIdx.y + i * 8;
        t[threadIdx.y + i * 8][threadIdx.x] = in[(size_t)yy * Cc + x];
    }
    __syncthreads();
    const int xo = blockIdx.y * 32 + threadIdx.x;
#pragma unroll
    for (int i = 0; i < 4; i++) {
        int yo = blockIdx.x * 32 + threadIdx.y + i * 8;
        out[(size_t)yo * Rr + xo] = __float2half(t[threadIdx.x][threadIdx.y + i * 8]);
    }
}

// ---------------- rmsnorm (+optional rope), f16 out ----------------------------
template<bool ROPE>
__global__ void rmsnorm_kernel(const float* __restrict__ x,
                               const float* __restrict__ gamma,
                               const int*   __restrict__ positions,
                               __half* __restrict__ out)
{
    __shared__ float sh[E_];
    __shared__ float warpsum[8];
    __shared__ float stot;
    const int row = blockIdx.x;
    const float* xr = x + (size_t)row * E_;

    float vals[E_/256];
    float ss = 0.f;
#pragma unroll
    for (int i = 0; i < E_/256; i++) {
        float v = xr[threadIdx.x + i*256];
        vals[i] = v;
        ss += v * v;
    }
#pragma unroll
    for (int o = 16; o; o >>= 1) ss += __shfl_xor_sync(0xffffffffu, ss, o);
    if ((threadIdx.x & 31) == 0) warpsum[threadIdx.x >> 5] = ss;
    __syncthreads();
    if (threadIdx.x == 0) {
        float t = 0.f;
#pragma unroll
        for (int i = 0; i < 8; i++) t += warpsum[i];
        stot = t;
    }
    __syncthreads();
    const float inv = rsqrtf(stot * (1.f / E_) + 1e-5f);

#pragma unroll
    for (int i = 0; i < E_/256; i++) {
        int e = threadIdx.x + i*256;
        sh[e] = vals[i] * inv * gamma[e];
    }
    __syncthreads();

    if (!ROPE) {
#pragma unroll
        for (int i = 0; i < E_/256; i++) {
            int e = threadIdx.x + i*256;
            out[(size_t)row*E_ + e] = __float2half(sh[e]);
        }
    } else {
        const int s = row % S_;
        const float pos = (float)positions[s];
#pragma unroll
        for (int i = 0; i < E_/256; i++) {
            int e = threadIdx.x + i*256;
            int d = e & 127;
            int d2 = d & 63;
            float ang = pos * expf(-(float)d2 * (9.210340371976184f / 64.f));
            float c = cosf(ang), sn = sinf(ang);
            float v = sh[e];
            float partner = (d < 64) ? -sh[e + 64] : sh[e - 64];
            out[(size_t)row*E_ + e] = __float2half(v * c + partner * sn);
        }
    }
}

// ---------------- causal softmax: f32 scores -> f16 probs ----------------------
__global__ void softmax_causal_kernel(const float* __restrict__ scores,
                                      __half* __restrict__ probs)
{
    __shared__ float warpred[8];
    __shared__ float sbc;
    const int r = blockIdx.x;
    const int z = blockIdx.y;
    const float* rowp = scores + ((size_t)z * S_ + r) * S_;
    __half* prow = probs + ((size_t)z * S_ + r) * S_;
    const int n = r + 1;
    const float scale = 0.08838834764831845f;

    float v[8];
    float m = -1e30f;
#pragma unroll
    for (int t = 0; t < 8; t++) {
        int j = threadIdx.x + t*256;
        if (j < n) { float s = rowp[j] * scale; v[t] = s; m = fmaxf(m, s); }
    }
#pragma unroll
    for (int o = 16; o; o >>= 1) m = fmaxf(m, __shfl_xor_sync(0xffffffffu, m, o));
    if ((threadIdx.x & 31) == 0) warpred[threadIdx.x >> 5] = m;
    __syncthreads();
    if (threadIdx.x == 0) {
        float t = -1e30f;
#pragma unroll
        for (int i = 0; i < 8; i++) t = fmaxf(t, warpred[i]);
        sbc = t;
    }
    __syncthreads();
    const float M = sbc;
    __syncthreads();

    float sum = 0.f;
#pragma unroll
    for (int t = 0; t < 8; t++) {
        int j = threadIdx.x + t*256;
        if (j < n) { float e = __expf(v[t] - M); v[t] = e; sum += e; }
    }
#pragma unroll
    for (int o = 16; o; o >>= 1) sum += __shfl_xor_sync(0xffffffffu, sum, o);
    if ((threadIdx.x & 31) == 0) warpred[threadIdx.x >> 5] = sum;
    __syncthreads();
    if (threadIdx.x == 0) {
        float t = 0.f;
#pragma unroll
        for (int i = 0; i < 8; i++) t += warpred[i];
        sbc = t;
    }
    __syncthreads();
    const float invS = 1.f / sbc;

#pragma unroll
    for (int t = 0; t < 8; t++) {
        int j = threadIdx.x + t*256;
        if (j < n) prow[j] = __float2half(v[t] * invS);
    }
    const int nend = (n + 127) & ~127;
    for (int j = n + threadIdx.x; j < nend; j += 256) prow[j] = __float2half(0.f);
}

// ---------------- driver --------------------------------------------------------
extern "C" void kernel_launch(void* const* d_in, const int* in_sizes, int n_in,
                              void* d_out, int out_size)
{
    const float* inputs     = (const float*)d_in[0];
    const float* gamma_attn = (const float*)d_in[1];
    const float* gamma_ffn  = (const float*)d_in[2];
    const float* wq         = (const float*)d_in[3];
    const float* wk         = (const float*)d_in[4];
    const float* wv         = (const float*)d_in[5];
    const float* wo         = (const float*)d_in[6];
    const float* w_gate     = (const float*)d_in[7];
    const float* w_lin      = (const float*)d_in[8];
    const float* w_out      = (const float*)d_in[9];
    const int*   positions  = (const int*)d_in[10];
    float* out = (float*)d_out;

    float *sc, *x2;
    __half *probsh, *yh, *qh, *kh, *vh, *attnh, *acth;
    __half *wqh, *wkh, *wvh, *woh, *wgh, *wlh, *wouth;
    cudaGetSymbolAddress((void**)&sc,   g_sc);
    cudaGetSymbolAddress((void**)&x2,   g_x2);
    cudaGetSymbolAddress((void**)&probsh, h_probs);
    cudaGetSymbolAddress((void**)&yh,    h_y);
    cudaGetSymbolAddress((void**)&qh,    h_q);
    cudaGetSymbolAddress((void**)&kh,    h_k);
    cudaGetSymbolAddress((void**)&vh,    h_v);
    cudaGetSymbolAddress((void**)&attnh, h_attn);
    cudaGetSymbolAddress((void**)&acth,  h_act);
    cudaGetSymbolAddress((void**)&wqh,   h_wq);
    cudaGetSymbolAddress((void**)&wkh,   h_wk);
    cudaGetSymbolAddress((void**)&wvh,   h_wv);
    cudaGetSymbolAddress((void**)&woh,   h_wo);
    cudaGetSymbolAddress((void**)&wgh,   h_wg);
    cudaGetSymbolAddress((void**)&wlh,   h_wl);
    cudaGetSymbolAddress((void**)&wouth, h_wout);

    cudaFuncSetAttribute((const void*)gemm_f16<true,false,false,false,true>,
                         cudaFuncAttributeMaxDynamicSharedMemorySize, SMEM_BYTES);
    cudaFuncSetAttribute((const void*)gemm_f16<true,true,false,false,false>,
                         cudaFuncAttributeMaxDynamicSharedMemorySize, SMEM_BYTES);
    cudaFuncSetAttribute((const void*)gemm_f16<false,false,true,false,true>,
                         cudaFuncAttributeMaxDynamicSharedMemorySize, SMEM_BYTES);
    cudaFuncSetAttribute((const void*)gemm_f16<true,false,false,true,false>,
                         cudaFuncAttributeMaxDynamicSharedMemorySize, SMEM_BYTES);
    cudaFuncSetAttribute((const void*)gemm_ffn1,
                         cudaFuncAttributeMaxDynamicSharedMemorySize, F1_SMEM);

    const long long SE  = (long long)S_ * E_;
    const long long SS2 = (long long)S_ * S_;
    const dim3 tb(32, 8);
    const long long Z0 = 0;

    // 0: y = rope(rmsnorm(x)) -> f16
    rmsnorm_kernel<true><<<MTOK, 256>>>(inputs, gamma_attn, positions, yh);

    // 1-2: wq/wk transposes
    tcvt_kernel<<<dim3(E_/32, E_/32), tb>>>(wq, wqh, E_, E_);
    tcvt_kernel<<<dim3(E_/32, E_/32), tb>>>(wk, wkh, E_, E_);

    // 3: gemm_q  (ncu capture candidate, skip=3)
    gemm_f16<true,false,false,false,true><<<dim3(E_/BN, MTOK/BM), 256, SMEM_BYTES>>>(
        yh, wqh, qh, nullptr, E_, E_, E_, E_, Z0,Z0,Z0,Z0,Z0,Z0);

    // 4: wv transpose
    tcvt_kernel<<<dim3(E_/32, E_/32), tb>>>(wv, wvh, E_, E_);

    // 5: gemm_k  (ncu capture candidate, skip=5)
    gemm_f16<true,false,false,false,true><<<dim3(E_/BN, MTOK/BM), 256, SMEM_BYTES>>>(
        yh, wkh, kh, nullptr, E_, E_, E_, E_, Z0,Z0,Z0,Z0,Z0,Z0);

    // 6: gemm_v
    gemm_f16<true,false,false,false,true><<<dim3(E_/BN, MTOK/BM), 256, SMEM_BYTES>>>(
        yh, wvh, vh, nullptr, E_, E_, E_, E_, Z0,Z0,Z0,Z0,Z0,Z0);

    // 7-10: remaining weight transposes
    tcvt_kernel<<<dim3(E_/32, E_/32), tb>>>(wo,     woh,   E_, E_);
    tcvt_kernel<<<dim3(F_/32, E_/32), tb>>>(w_gate, wgh,   E_, F_);
    tcvt_kernel<<<dim3(F_/32, E_/32), tb>>>(w_lin,  wlh,   E_, F_);
    tcvt_kernel<<<dim3(E_/32, F_/32), tb>>>(w_out,  wouth, F_, E_);

    // 11: scores = q @ k^T per (b,h), lower-triangular tiles only (f32 out)
    gemm_f16<true,true,false,false,false><<<dim3(S_/BN, S_/BM, B_*H_), 256, SMEM_BYTES>>>(
        qh, kh, sc, nullptr, DH_, E_, E_, S_,
        SE, DH_, SE, DH_, 16*SS2, SS2);

    // 12: causal softmax, f16 probs (+128-boundary zero fill)
    softmax_causal_kernel<<<dim3(S_, B_*H_), 256>>>(sc, probsh);

    // 13: attn = probs @ v per (b,h), causal K-limit, f16 out
    gemm_f16<false,false,true,false,true><<<dim3(1, S_/BM, B_*H_), 256, SMEM_BYTES>>>(
        probsh, vh, attnh, nullptr, S_, S_, E_, E_,
        16*SS2, SS2, SE, DH_, SE, DH_);

    // 14: x2 = attn @ wo^T + inputs (f32 out, residual fused)
    gemm_f16<true,false,false,true,false><<<dim3(E_/BN, MTOK/BM), 256, SMEM_BYTES>>>(
        attnh, woh, x2, inputs, E_, E_, E_, E_, Z0,Z0,Z0,Z0,Z0,Z0);

    // 15: y2 = rmsnorm(x2) -> f16 (reuse yh)
    rmsnorm_kernel<false><<<MTOK, 256>>>(x2, gamma_ffn, positions, yh);

    // 16: act = gelu(y2 @ wg^T) * (y2 @ wl^T)  (fused, f16 out)
    gemm_ffn1<<<dim3(F_/BN, MTOK/BM), 256, F1_SMEM>>>(yh, wgh, wlh, acth, E_, F_);

    // 17: out = act @ w_out^T + x2 (f32 out, residual fused)
    gemm_f16<true,false,false,true,false><<<dim3(E_/BN, MTOK/BM), 256, SMEM_BYTES>>>(
        acth, wouth, out, x2, F_, F_, F_, E_, Z0,Z0,Z0,Z0,Z0,Z0);
}

// round 14
// speedup vs baseline: 1.0027x; 1.0027x over previous
#include <cuda_runtime.h>
#include <cuda_fp16.h>
#include <mma.h>
#include <cstdint>

using namespace nvcuda;

// Problem dims
#define B_ 4
#define S_ 2048
#define E_ 2048
#define H_ 16
#define DH_ 128
#define F_ 8192
#define MTOK (B_*S_)   // 8192 token rows

// ---------------- scratch (static device globals; no allocations) -------------
__device__ float  g_sc  [(size_t)B_*H_*S_*S_];        // 1GB scores f32
__device__ float  g_x2  [(size_t)MTOK*E_];            // 64MB

__device__ __half h_probs[(size_t)B_*H_*S_*S_];       // 512MB f16 probs
__device__ __half h_y   [(size_t)MTOK*E_];            // 32MB (y / y2)
__device__ __half h_q   [(size_t)MTOK*E_];
__device__ __half h_k   [(size_t)MTOK*E_];
__device__ __half h_v   [(size_t)MTOK*E_];
__device__ __half h_attn[(size_t)MTOK*E_];
__device__ __half h_act [(size_t)MTOK*F_];            // 128MB
__device__ __half h_wq  [(size_t)E_*E_];              // [N][K] f16
__device__ __half h_wk  [(size_t)E_*E_];
__device__ __half h_wv  [(size_t)E_*E_];
__device__ __half h_wo  [(size_t)E_*E_];
__device__ __half h_wg  [(size_t)E_*F_];              // [8192][2048]
__device__ __half h_wl  [(size_t)E_*F_];
__device__ __half h_wout[(size_t)F_*E_];              // [2048][8192]

// single TU-wide dynamic smem symbol
extern __shared__ char dynsmem[];

// ---------------- cp.async helpers --------------------------------------------
__device__ __forceinline__ void cpa16(void* dst, const void* src) {
    unsigned d = (unsigned)__cvta_generic_to_shared(dst);
    asm volatile("cp.async.cg.shared.global [%0], [%1], 16;\n" :: "r"(d), "l"(src));
}
__device__ __forceinline__ void cpa_commit() {
    asm volatile("cp.async.commit_group;\n" ::: "memory");
}
template<int N>
__device__ __forceinline__ void cpa_wait() {
    asm volatile("cp.async.wait_group %0;\n" :: "n"(N) : "memory");
}

// ---------------- fp16 WMMA GEMM, cp.async 3-stage, single-barrier loop --------
// C = A(f16) * B(f16) (+R f32). TRANS_B: B is [N][K] row-major.
// OUT_HALF: write f16 via smem-staged convert epilogue; else f32.
// BM=BN=128, BK=64. 256 threads = 8 warps (2x4), warp tile 64x32 (m16n16k16).
#define BM 128
#define BN 128
#define BK 64
#define HLDA 72                    // A/Bt smem row pitch (halves)
#define HLDB 136                   // non-trans B smem row pitch
#define A_H (BM*HLDA)              // 9216 halves
#define B_H (BM*HLDA)              // 9216 halves (covers both layouts)
#define STG_H (A_H + B_H)          // 18432 halves = 36864 B
#define NSTAGE 3
#define SMEM_BYTES (NSTAGE*STG_H*2)   // 110592 B
#define CLDS 136                   // f32 epilogue staging pitch

template<bool TRANS_B, bool CAUSAL_SKIP, bool CAUSAL_KLIM, bool HAS_RES, bool OUT_HALF>
__global__ void __launch_bounds__(256, 2)
gemm_f16(const __half* __restrict__ A, const __half* __restrict__ Bm,
         void* __restrict__ Cv, const float* __restrict__ R,
         int K, int lda, int ldb, int ldc,
         long long sAo, long long sAi,
         long long sBo, long long sBi,
         long long sCo, long long sCi)
{
    if (CAUSAL_SKIP && blockIdx.x > blockIdx.y) return;

    __half* smem = (__half*)dynsmem;

    const int zb = blockIdx.z >> 4, zi = blockIdx.z & 15;
    const long long offA = zb*sAo + (long long)zi*sAi;
    const long long offB = zb*sBo + (long long)zi*sBi;
    const long long offC = zb*sCo + (long long)zi*sCi;

    const __half* Ag = A + offA + (long long)blockIdx.y * BM * lda;
    const int n0 = blockIdx.x * BN;
    const __half* Bg = TRANS_B ? (Bm + offB + (long long)n0 * ldb)
                               : (Bm + offB + n0);

    int kEnd = K;
    if (CAUSAL_KLIM) kEnd = min(K, (int)(blockIdx.y + 1) * BM);
    const int nk = kEnd / BK;

    const int tid = threadIdx.x;
    const int warpId  = tid >> 5;
    const int warpRow = warpId >> 2;   // 0..1
    const int warpCol = warpId & 3;    // 0..3

    wmma::fragment<wmma::accumulator, 16, 16, 16, float> acc[4][2];
#pragma unroll
    for (int i = 0; i < 4; i++)
#pragma unroll
        for (int j = 0; j < 2; j++)
            wmma::fill_fragment(acc[i][j], 0.f);

    auto issue = [&](int kc, int st) {
        __half* da = smem + st * STG_H;
        __half* db = da + A_H;
#pragma unroll
        for (int t = 0; t < 4; t++) {            // A: 1024 x 16B
            int qq = tid + t * 256;
            int row = qq >> 3, c16 = qq & 7;
            cpa16(da + row * HLDA + c16 * 8,
                  Ag + (long long)row * lda + kc * BK + c16 * 8);
        }
        if (TRANS_B) {
#pragma unroll
            for (int t = 0; t < 4; t++) {        // Bt: [128 n-rows][64 k]
                int qq = tid + t * 256;
                int row = qq >> 3, c16 = qq & 7;
                cpa16(db + row * HLDA + c16 * 8,
                      Bg + (long long)row * ldb + kc * BK + c16 * 8);
            }
        } else {
#pragma unroll
            for (int t = 0; t < 4; t++) {        // B: [64 k-rows][128 n]
                int qq = tid + t * 256;
                int row = qq >> 4, c16 = qq & 15;
                cpa16(db + row * HLDB + c16 * 8,
                      Bg + (long long)(kc * BK + row) * ldb + c16 * 8);
            }
        }
    };

    auto compute = [&](int buf) {
        const __half* Asb = smem + buf * STG_H + warpRow * 64 * HLDA;
        const __half* Bsb = smem + buf * STG_H + A_H;
#pragma unroll
        for (int ks = 0; ks < BK/16; ks++) {
            wmma::fragment<wmma::matrix_a, 16, 16, 16, __half, wmma::row_major> af[4];
#pragma unroll
            for (int i = 0; i < 4; i++)
                wmma::load_matrix_sync(af[i], Asb + i*16*HLDA + ks*16, HLDA);
            if (TRANS_B) {
                wmma::fragment<wmma::matrix_b, 16, 16, 16, __half, wmma::col_major> bf[2];
#pragma unroll
                for (int j = 0; j < 2; j++)
                    wmma::load_matrix_sync(bf[j], Bsb + (warpCol*32 + j*16)*HLDA + ks*16, HLDA);
#pragma unroll
                for (int i = 0; i < 4; i++)
#pragma unroll
                    for (int j = 0; j < 2; j++)
                        wmma::mma_sync(acc[i][j], af[i], bf[j], acc[i][j]);
            } else {
                wmma::fragment<wmma::matrix_b, 16, 16, 16, __half, wmma::row_major> bf[2];
#pragma unroll
                for (int j = 0; j < 2; j++)
                    wmma::load_matrix_sync(bf[j], Bsb + ks*16*HLDB + warpCol*32 + j*16, HLDB);
#pragma unroll
                for (int i = 0; i < 4; i++)
#pragma unroll
                    for (int j = 0; j < 2; j++)
                        wmma::mma_sync(acc[i][j], af[i], bf[j], acc[i][j]);
            }
        }
    };

    // prologue: prefetch 2 stages
    issue(0, 0); cpa_commit();
    if (1 < nk) issue(1, 1);
    cpa_commit();

    // single-barrier mainloop: issue next stage right after the barrier
    for (int kc = 0; kc < nk; kc++) {
        cpa_wait<NSTAGE-2>();        // stage kc landed (this thread's groups)
        __syncthreads();             // ...and everyone else's
        if (kc + 2 < nk) issue(kc + 2, (kc + 2) % NSTAGE);
        cpa_commit();
        compute(kc % NSTAGE);
    }

    const long long crow = (long long)blockIdx.y * BM + warpRow * 64;
    const int ccol = n0 + warpCol * 32;

    if (!OUT_HALF) {
        float* Cg = (float*)Cv + offC;
#pragma unroll
        for (int i = 0; i < 4; i++) {
#pragma unroll
            for (int j = 0; j < 2; j++) {
                long long offc = (crow + i*16) * ldc + ccol + j*16;
                if (HAS_RES) {
                    wmma::fragment<wmma::accumulator, 16, 16, 16, float> rf;
                    wmma::load_matrix_sync(rf, R + offc, ldc, wmma::mem_row_major);
#pragma unroll
                    for (int e = 0; e < rf.num_elements; e++)
                        acc[i][j].x[e] += rf.x[e];
                }
                wmma::store_matrix_sync(Cg + offc, acc[i][j], ldc, wmma::mem_row_major);
            }
        }
    } else {
        cpa_wait<0>();
        __syncthreads();
        float* cs = (float*)dynsmem;   // [128][CLDS]
#pragma unroll
        for (int i = 0; i < 4; i++)
#pragma unroll
            for (int j = 0; j < 2; j++)
                wmma::store_matrix_sync(cs + (warpRow*64 + i*16)*CLDS + warpCol*32 + j*16,
                                        acc[i][j], CLDS, wmma::mem_row_major);
        __syncthreads();
        __half* Ch = (__half*)Cv + offC;
        const long long row0 = (long long)blockIdx.y * BM;
#pragma unroll
        for (int t = 0; t < 8; t++) {
            int qq = tid + t * 256;
            int row = qq >> 4, c = (qq & 15) * 8;
            float4 lo = *(float4*)(cs + row * CLDS + c);
            float4 hi = *(float4*)(cs + row * CLDS + c + 4);
            __half2 p0 = __floats2half2_rn(lo.x, lo.y);
            __half2 p1 = __floats2half2_rn(lo.z, lo.w);
            __half2 p2 = __floats2half2_rn(hi.x, hi.y);
            __half2 p3 = __floats2half2_rn(hi.z, hi.w);
            uint4 pk;
            pk.x = *(unsigned*)&p0; pk.y = *(unsigned*)&p1;
            pk.z = *(unsigned*)&p2; pk.w = *(unsigned*)&p3;
            *(uint4*)(Ch + (row0 + row) * ldc + n0 + c) = pk;
        }
    }
}

// ---------------- fused FFN1: act = gelu(A@Wg^T) * (A@Wl^T), f16 out -----------
// Shared A tile, two B streams, dual accumulators, gelu*mul epilogue.
#define F1_STG_H (3*BM*HLDA)                 // A + Bg + Bl per stage (halves)
#define F1_SMEM (NSTAGE*F1_STG_H*2)          // 165888 B

__global__ void __launch_bounds__(256, 1)
gemm_ffn1(const __half* __restrict__ A, const __half* __restrict__ Wg,
          const __half* __restrict__ Wl, __half* __restrict__ Out,
          int K, int ldout)
{
    __half* smem = (__half*)dynsmem;

    const __half* Ag  = A  + (size_t)blockIdx.y * BM * K;
    const int n0 = blockIdx.x * BN;
    const __half* Bgg = Wg + (size_t)n0 * K;
    const __half* Blg = Wl + (size_t)n0 * K;
    const int nk = K / BK;

    const int tid = threadIdx.x;
    const int warpId  = tid >> 5;
    const int warpRow = warpId >> 2;
    const int warpCol = warpId & 3;

    wmma::fragment<wmma::accumulator, 16, 16, 16, float> accG[4][2], accL[4][2];
#pragma unroll
    for (int i = 0; i < 4; i++)
#pragma unroll
        for (int j = 0; j < 2; j++) {
            wmma::fill_fragment(accG[i][j], 0.f);
            wmma::fill_fragment(accL[i][j], 0.f);
        }

    auto issue = [&](int kc, int st) {
        __half* da = smem + st * F1_STG_H;
        __half* dg = da + A_H;
        __half* dl = dg + A_H;
#pragma unroll
        for (int t = 0; t < 4; t++) {
            int qq = tid + t * 256;
            int row = qq >> 3, c16 = qq & 7;
            cpa16(da + row * HLDA + c16 * 8, Ag  + (long long)row * K + kc * BK + c16 * 8);
            cpa16(dg + row * HLDA + c16 * 8, Bgg + (long long)row * K + kc * BK + c16 * 8);
            cpa16(dl + row * HLDA + c16 * 8, Blg + (long long)row * K + kc * BK + c16 * 8);
        }
    };

    auto compute = [&](int buf) {
        const __half* Asb = smem + buf * F1_STG_H + warpRow * 64 * HLDA;
        const __half* Gsb = smem + buf * F1_STG_H + A_H;
        const __half* Lsb = Gsb + A_H;
#pragma unroll
        for (int ks = 0; ks < BK/16; ks++) {
            wmma::fragment<wmma::matrix_a, 16, 16, 16, __half, wmma::row_major> af[4];
#pragma unroll
            for (int i = 0; i < 4; i++)
                wmma::load_matrix_sync(af[i], Asb + i*16*HLDA + ks*16, HLDA);
            {
                wmma::fragment<wmma::matrix_b, 16, 16, 16, __half, wmma::col_major> bf[2];
#pragma unroll
                for (int j = 0; j < 2; j++)
                    wmma::load_matrix_sync(bf[j], Gsb + (warpCol*32 + j*16)*HLDA + ks*16, HLDA);
#pragma unroll
                for (int i = 0; i < 4; i++)
#pragma unroll
                    for (int j = 0; j < 2; j++)
                        wmma::mma_sync(accG[i][j], af[i], bf[j], accG[i][j]);
            }
            {
                wmma::fragment<wmma::matrix_b, 16, 16, 16, __half, wmma::col_major> bf[2];
#pragma unroll
                for (int j = 0; j < 2; j++)
                    wmma::load_matrix_sync(bf[j], Lsb + (warpCol*32 + j*16)*HLDA + ks*16, HLDA);
#pragma unroll
                for (int i = 0; i < 4; i++)
#pragma unroll
                    for (int j = 0; j < 2; j++)
                        wmma::mma_sync(accL[i][j], af[i], bf[j], accL[i][j]);
            }
        }
    };

    issue(0, 0); cpa_commit();
    issue(1, 1); cpa_commit();
    for (int kc = 0; kc < nk; kc++) {
        cpa_wait<NSTAGE-2>();
        __syncthreads();
        if (kc + 2 < nk) issue(kc + 2, (kc + 2) % NSTAGE);
        cpa_commit();
        compute(kc % NSTAGE);
    }

    // epilogue: stage both accumulator sets, gelu*mul, store f16
    cpa_wait<0>();
    __syncthreads();
    float* csG = (float*)dynsmem;            // [128][CLDS]
    float* csL = csG + 128*CLDS;             // [128][CLDS]
#pragma unroll
    for (int i = 0; i < 4; i++)
#pragma unroll
        for (int j = 0; j < 2; j++) {
            wmma::store_matrix_sync(csG + (warpRow*64 + i*16)*CLDS + warpCol*32 + j*16,
                                    accG[i][j], CLDS, wmma::mem_row_major);
            wmma::store_matrix_sync(csL + (warpRow*64 + i*16)*CLDS + warpCol*32 + j*16,
                                    accL[i][j], CLDS, wmma::mem_row_major);
        }
    __syncthreads();
    const long long row0 = (long long)blockIdx.y * BM;
#pragma unroll
    for (int t = 0; t < 8; t++) {
        int qq = tid + t * 256;
        int row = qq >> 4, c = (qq & 15) * 8;
        float g[8], l[8];
        *(float4*)(g)   = *(float4*)(csG + row * CLDS + c);
        *(float4*)(g+4) = *(float4*)(csG + row * CLDS + c + 4);
        *(float4*)(l)   = *(float4*)(csL + row * CLDS + c);
        *(float4*)(l+4) = *(float4*)(csL + row * CLDS + c + 4);
        __half hv[8];
#pragma unroll
        for (int e = 0; e < 8; e++) {
            float a = g[e];
            a = 0.5f * a * (1.f + erff(a * 0.70710678118654752f)) * l[e];
            hv[e] = __float2half(a);
        }
        *(uint4*)(Out + (row0 + row) * ldout + n0 + c) = *(uint4*)hv;
    }
}

// ---------------- transpose + f32->f16 convert ---------------------------------
__global__ void tcvt_kernel(const float* __restrict__ in, __half* __restrict__ out,
                            int Rr, int Cc)
{
    __shared__ float t[32][33];
    const int x = blockIdx.x * 32 + threadIdx.x;
#pragma unroll
    for (int i = 0; i < 4; i++) {
        int yy = blockIdx.y * 32 + threadIdx.y + i * 8;
        t[threadIdx.y + i * 8][threadIdx.x] = in[(size_t)yy * Cc + x];
    }
    __syncthreads();
    const int xo = blockIdx.y * 32 + threadIdx.x;
#pragma unroll
    for (int i = 0; i < 4; i++) {
        int yo = blockIdx.x * 32 + threadIdx.y + i * 8;
        out[(size_t)yo * Rr + xo] = __float2half(t[threadIdx.x][threadIdx.y + i * 8]);
    }
}

// ---------------- rmsnorm (+optional rope), f16 out ----------------------------
template<bool ROPE>
__global__ void rmsnorm_kernel(const float* __restrict__ x,
                               const float* __restrict__ gamma,
                               const int*   __restrict__ positions,
                               __half* __restrict__ out)
{
    __shared__ float sh[E_];
    __shared__ float warpsum[8];
    __shared__ float stot;
    const int row = blockIdx.x;
    const float* xr = x + (size_t)row * E_;

    float vals[E_/256];
    float ss = 0.f;
#pragma unroll
    for (int i = 0; i < E_/256; i++) {
        float v = xr[threadIdx.x + i*256];
        vals[i] = v;
        ss += v * v;
    }
#pragma unroll
    for (int o = 16; o; o >>= 1) ss += __shfl_xor_sync(0xffffffffu, ss, o);
    if ((threadIdx.x & 31) == 0) warpsum[threadIdx.x >> 5] = ss;
    __syncthreads();
    if (threadIdx.x == 0) {
        float t = 0.f;
#pragma unroll
        for (int i = 0; i < 8; i++) t += warpsum[i];
        stot = t;
    }
    __syncthreads();
    const float inv = rsqrtf(stot * (1.f / E_) + 1e-5f);

#pragma unroll
    for (int i = 0; i < E_/256; i++) {
        int e = threadIdx.x + i*256;
        sh[e] = vals[i] * inv * gamma[e];
    }
    __syncthreads();

    if (!ROPE) {
#pragma unroll
        for (int i = 0; i < E_/256; i++) {
            int e = threadIdx.x + i*256;
            out[(size_t)row*E_ + e] = __float2half(sh[e]);
        }
    } else {
        const int s = row % S_;
        const float pos = (float)positions[s];
#pragma unroll
        for (int i = 0; i < E_/256; i++) {
            int e = threadIdx.x + i*256;
            int d = e & 127;
            int d2 = d & 63;
            float ang = pos * expf(-(float)d2 * (9.210340371976184f / 64.f));
            float c = cosf(ang), sn = sinf(ang);
            float v = sh[e];
            float partner = (d < 64) ? -sh[e + 64] : sh[e - 64];
            out[(size_t)row*E_ + e] = __float2half(v * c + partner * sn);
        }
    }
}

// ---------------- causal softmax: f32 scores -> f16 probs ----------------------
__global__ void softmax_causal_kernel(const float* __restrict__ scores,
                                      __half* __restrict__ probs)
{
    __shared__ float warpred[8];
    __shared__ float sbc;
    const int r = blockIdx.x;
    const int z = blockIdx.y;
    const float* rowp = scores + ((size_t)z * S_ + r) * S_;
    __half* prow = probs + ((size_t)z * S_ + r) * S_;
    const int n = r + 1;
    const float scale = 0.08838834764831845f;

    float v[8];
    float m = -1e30f;
#pragma unroll
    for (int t = 0; t < 8; t++) {
        int j = threadIdx.x + t*256;
        if (j < n) { float s = rowp[j] * scale; v[t] = s; m = fmaxf(m, s); }
    }
#pragma unroll
    for (int o = 16; o; o >>= 1) m = fmaxf(m, __shfl_xor_sync(0xffffffffu, m, o));
    if ((threadIdx.x & 31) == 0) warpred[threadIdx.x >> 5] = m;
    __syncthreads();
    if (threadIdx.x == 0) {
        float t = -1e30f;
#pragma unroll
        for (int i = 0; i < 8; i++) t = fmaxf(t, warpred[i]);
        sbc = t;
    }
    __syncthreads();
    const float M = sbc;
    __syncthreads();

    float sum = 0.f;
#pragma unroll
    for (int t = 0; t < 8; t++) {
        int j = threadIdx.x + t*256;
        if (j < n) { float e = __expf(v[t] - M); v[t] = e; sum += e; }
    }
#pragma unroll
    for (int o = 16; o; o >>= 1) sum += __shfl_xor_sync(0xffffffffu, sum, o);
    if ((threadIdx.x & 31) == 0) warpred[threadIdx.x >> 5] = sum;
    __syncthreads();
    if (threadIdx.x == 0) {
        float t = 0.f;
#pragma unroll
        for (int i = 0; i < 8; i++) t += warpred[i];
        sbc = t;
    }
    __syncthreads();
    const float invS = 1.f / sbc;

#pragma unroll
    for (int t = 0; t < 8; t++) {
        int j = threadIdx.x + t*256;
        if (j < n) prow[j] = __float2half(v[t] * invS);
    }
    const int nend = (n + 127) & ~127;
    for (int j = n + threadIdx.x; j < nend; j += 256) prow[j] = __float2half(0.f);
}

// ---------------- driver --------------------------------------------------------
extern "C" void kernel_launch(void* const* d_in, const int* in_sizes, int n_in,
                              void* d_out, int out_size)
{
    const float* inputs     = (const float*)d_in[0];
    const float* gamma_attn = (const float*)d_in[1];
    const float* gamma_ffn  = (const float*)d_in[2];
    const float* wq         = (const float*)d_in[3];
    const float* wk         = (const float*)d_in[4];
    const float* wv         = (const float*)d_in[5];
    const float* wo         = (const float*)d_in[6];
    const float* w_gate     = (const float*)d_in[7];
    const float* w_lin      = (const float*)d_in[8];
    const float* w_out      = (const float*)d_in[9];
    const int*   positions  = (const int*)d_in[10];
    float* out = (float*)d_out;

    float *sc, *x2;
    __half *probsh, *yh, *qh, *kh, *vh, *attnh, *acth;
    __half *wqh, *wkh, *wvh, *woh, *wgh, *wlh, *wouth;
    cudaGetSymbolAddress((void**)&sc,   g_sc);
    cudaGetSymbolAddress((void**)&x2,   g_x2);
    cudaGetSymbolAddress((void**)&probsh, h_probs);
    cudaGetSymbolAddress((void**)&yh,    h_y);
    cudaGetSymbolAddress((void**)&qh,    h_q);
    cudaGetSymbolAddress((void**)&kh,    h_k);
    cudaGetSymbolAddress((void**)&vh,    h_v);
    cudaGetSymbolAddress((void**)&attnh, h_attn);
    cudaGetSymbolAddress((void**)&acth,  h_act);
    cudaGetSymbolAddress((void**)&wqh,   h_wq);
    cudaGetSymbolAddress((void**)&wkh,   h_wk);
    cudaGetSymbolAddress((void**)&wvh,   h_wv);
    cudaGetSymbolAddress((void**)&woh,   h_wo);
    cudaGetSymbolAddress((void**)&wgh,   h_wg);
    cudaGetSymbolAddress((void**)&wlh,   h_wl);
    cudaGetSymbolAddress((void**)&wouth, h_wout);

    cudaFuncSetAttribute((const void*)gemm_f16<true,false,false,false,true>,
                         cudaFuncAttributeMaxDynamicSharedMemorySize, SMEM_BYTES);
    cudaFuncSetAttribute((const void*)gemm_f16<true,true,false,false,false>,
                         cudaFuncAttributeMaxDynamicSharedMemorySize, SMEM_BYTES);
    cudaFuncSetAttribute((const void*)gemm_f16<false,false,true,false,true>,
                         cudaFuncAttributeMaxDynamicSharedMemorySize, SMEM_BYTES);
    cudaFuncSetAttribute((const void*)gemm_f16<true,false,false,true,false>,
                         cudaFuncAttributeMaxDynamicSharedMemorySize, SMEM_BYTES);
    cudaFuncSetAttribute((const void*)gemm_ffn1,
                         cudaFuncAttributeMaxDynamicSharedMemorySize, F1_SMEM);

    const long long SE  = (long long)S_ * E_;
    const long long SS2 = (long long)S_ * S_;
    const dim3 tb(32, 8);
    const long long Z0 = 0;

    // 0: y = rope(rmsnorm(x)) -> f16
    rmsnorm_kernel<true><<<MTOK, 256>>>(inputs, gamma_attn, positions, yh);

    // 1-2: wq/wk transposes
    tcvt_kernel<<<dim3(E_/32, E_/32), tb>>>(wq, wqh, E_, E_);
    tcvt_kernel<<<dim3(E_/32, E_/32), tb>>>(wk, wkh, E_, E_);

    // 3: gemm_q  (ncu capture candidate, skip=3)
    gemm_f16<true,false,false,false,true><<<dim3(E_/BN, MTOK/BM), 256, SMEM_BYTES>>>(
        yh, wqh, qh, nullptr, E_, E_, E_, E_, Z0,Z0,Z0,Z0,Z0,Z0);

    // 4: wv transpose
    tcvt_kernel<<<dim3(E_/32, E_/32), tb>>>(wv, wvh, E_, E_);

    // 5: gemm_k  (ncu capture candidate, skip=5)
    gemm_f16<true,false,false,false,true><<<dim3(E_/BN, MTOK/BM), 256, SMEM_BYTES>>>(
        yh, wkh, kh, nullptr, E_, E_, E_, E_, Z0,Z0,Z0,Z0,Z0,Z0);

    // 6: gemm_v
    gemm_f16<true,false,false,false,true><<<dim3(E_/BN, MTOK/BM), 256, SMEM_BYTES>>>(
        yh, wvh, vh, nullptr, E_, E_, E_, E_, Z0,Z0,Z0,Z0,Z0,Z0);

    // 7-10: remaining weight transposes
    tcvt_kernel<<<dim3(E_/32, E_/32), tb>>>(wo,     woh,   E_, E_);
    tcvt_kernel<<<dim3(F_/32, E_/32), tb>>>(w_gate, wgh,   E_, F_);
    tcvt_kernel<<<dim3(F_/32, E_/32), tb>>>(w_lin,  wlh,   E_, F_);
    tcvt_kernel<<<dim3(E_/32, F_/32), tb>>>(w_out,  wouth, F_, E_);

    // 11: scores = q @ k^T per (b,h), lower-triangular tiles only (f32 out)
    gemm_f16<true,true,false,false,false><<<dim3(S_/BN, S_/BM, B_*H_), 256, SMEM_BYTES>>>(
        qh, kh, sc, nullptr, DH_, E_, E_, S_,
        SE, DH_, SE, DH_, 16*SS2, SS2);

    // 12: causal softmax, f16 probs (+128-boundary zero fill)
    softmax_causal_kernel<<<dim3(S_, B_*H_), 256>>>(sc, probsh);

    // 13: attn = probs @ v per (b,h), causal K-limit, f16 out
    gemm_f16<false,false,true,false,true><<<dim3(1, S_/BM, B_*H_), 256, SMEM_BYTES>>>(
        probsh, vh, attnh, nullptr, S_, S_, E_, E_,
        16*SS2, SS2, SE, DH_, SE, DH_);

    // 14: x2 = attn @ wo^T + inputs (f32 out, residual fused)
    gemm_f16<true,false,false,true,false><<<dim3(E_/BN, MTOK/BM), 256, SMEM_BYTES>>>(
        attnh, woh, x2, inputs, E_, E_, E_, E_, Z0,Z0,Z0,Z0,Z0,Z0);

    // 15: y2 = rmsnorm(x2) -> f16 (reuse yh)
    rmsnorm_kernel<false><<<MTOK, 256>>>(x2, gamma_ffn, positions, yh);

    // 16: act = gelu(y2 @ wg^T) * (y2 @ wl^T)  (fused, f16 out)
    gemm_ffn1<<<dim3(F_/BN, MTOK/BM), 256, F1_SMEM>>>(yh, wgh, wlh, acth, E_, F_);

    // 17: out = act @ w_out^T + x2 (f32 out, residual fused)
    gemm_f16<true,false,false,true,false><<<dim3(E_/BN, MTOK/BM), 256, SMEM_BYTES>>>(
        acth, wouth, out, x2, F_, F_, F_, E_, Z0,Z0,Z0,Z0,Z0,Z0);
}